// round 10
// baseline (speedup 1.0000x reference)
#include <cuda_runtime.h>

#define E_EDGES 262144
#define DMODEL  128
#define NNODES  65536
#define LN_EPSF 1e-5f
#define SCALEF  0.17677669529663687f   // 1/sqrt(32)
#define NTILES  4096                   // 64-edge tiles
#define PGRID   152

// ---------------- scratch (device globals; no allocations allowed) ----------
__device__ float g_S[(size_t)NNODES * DMODEL];    // sum exp(s)*V per node
__device__ float g_den[(size_t)NNODES * 4];       // sum exp(s) per node/head
__device__ float g_T[(size_t)NNODES * DMODEL];    // (0.5*S/den) @ Wo per node
__device__ float g_Wt[4][DMODEL][DMODEL];         // tf32, transposed, paired-k swizzle
__device__ int   g_is64;

// ---------------- helpers ----------------------------------------------------
__device__ __forceinline__ float to_tf32(float x) {
    float r; asm("cvt.rna.tf32.f32 %0, %1;" : "=f"(r) : "f"(x)); return r;
}

__device__ __forceinline__ void mma_tf32(float c[4], const unsigned a[4],
                                         unsigned b0, unsigned b1) {
    asm volatile(
        "mma.sync.aligned.m16n8k8.row.col.f32.tf32.tf32.f32 "
        "{%0,%1,%2,%3}, {%4,%5,%6,%7}, {%8,%9}, {%0,%1,%2,%3};"
        : "+f"(c[0]), "+f"(c[1]), "+f"(c[2]), "+f"(c[3])
        : "r"(a[0]), "r"(a[1]), "r"(a[2]), "r"(a[3]), "r"(b0), "r"(b1));
}

__device__ __forceinline__ void ldsm4(unsigned r[4], unsigned addr) {
    asm volatile("ldmatrix.sync.aligned.m8n8.x4.shared.b16 {%0,%1,%2,%3}, [%4];"
                 : "=r"(r[0]), "=r"(r[1]), "=r"(r[2]), "=r"(r[3]) : "r"(addr));
}

__device__ __forceinline__ void red_add_v4(float* p, float x, float y, float z, float w) {
    asm volatile("red.global.add.v4.f32 [%0], {%1,%2,%3,%4};"
                 :: "l"(p), "f"(x), "f"(y), "f"(z), "f"(w) : "memory");
}
__device__ __forceinline__ void red_add_f(float* p, float v) {
    asm volatile("red.global.add.f32 [%0], %1;" :: "l"(p), "f"(v) : "memory");
}

__device__ __forceinline__ void cp_async16(float* smem_dst, const float* gsrc) {
    unsigned s = (unsigned)__cvta_generic_to_shared(smem_dst);
    asm volatile("cp.async.cg.shared.global [%0], [%1], 16;" :: "r"(s), "l"(gsrc));
}
__device__ __forceinline__ void cp_commit() {
    asm volatile("cp.async.commit_group;");
}
template <int N>
__device__ __forceinline__ void cp_wait() {
    asm volatile("cp.async.wait_group %0;" :: "n"(N));
}

__device__ __forceinline__ int node_of(const void* idx, int is64, size_t pos) {
    return is64 ? (int)__ldg((const long long*)idx + pos)
                : __ldg((const int*)idx + pos);
}

// Unified tf32 GEMM core over a 64-row A tile (swizzle ^((r&7)<<2), stride 128)
// and G weight matrices in paired-k layout. Warp grid 2m x 4n, m32 x n32/warp.
// A fragments via ldmatrix.x4 (one LDSM per (kk, mi)); B via LDS.128 covering
// two kk steps. Low register pressure: G<=2 accumulator sets.
template <int G>
__device__ __forceinline__ void gemm_core(unsigned asB,
                                          const float* __restrict__ W0,
                                          const float* __restrict__ W1,
                                          float acc[][2][4][4],
                                          int wm, int wn, int lane) {
    const float* Wg[2] = {W0, W1};
    int tg = lane & 3;
    // ldmatrix source-lane roles
    int li = lane & 7;                  // row within 8-row block
    int lj = (lane >> 3) & 1;           // +8 row block
    int dk = (lane >> 4) << 2;          // k offset 0 or 4
    int sw = li << 2;                   // per-row swizzle
    unsigned aAddr0 = asB + (unsigned)((wm * 32 + lj * 8 + li) * 128) * 4u;
    unsigned aAddr1 = aAddr0 + 16u * 128u * 4u;

    #pragma unroll
    for (int g = 0; g < G; ++g)
        #pragma unroll
        for (int mi = 0; mi < 2; ++mi)
            #pragma unroll
            for (int ni = 0; ni < 4; ++ni)
                #pragma unroll
                for (int q = 0; q < 4; ++q) acc[g][mi][ni][q] = 0.f;

    #pragma unroll
    for (int p = 0; p < 8; ++p) {
        float4 bf[G][4];
        #pragma unroll
        for (int g = 0; g < G; ++g)
            #pragma unroll
            for (int ni = 0; ni < 4; ++ni) {
                int n = wn * 32 + ni * 8 + (lane >> 2);
                bf[g][ni] = *(const float4*)(Wg[g] + n * 128 +
                              ((p * 16 + 4 * tg) ^ ((n & 1) << 4)));
            }
        #pragma unroll
        for (int kh = 0; kh < 2; ++kh) {
            int k0 = p * 16 + kh * 8;
            unsigned koff = (unsigned)((k0 + dk) ^ sw) * 4u;
            unsigned a0[4], a1[4];
            ldsm4(a0, aAddr0 + koff);
            ldsm4(a1, aAddr1 + koff);
            #pragma unroll
            for (int g = 0; g < G; ++g)
                #pragma unroll
                for (int ni = 0; ni < 4; ++ni) {
                    unsigned b0 = __float_as_uint(kh ? bf[g][ni].z : bf[g][ni].x);
                    unsigned b1 = __float_as_uint(kh ? bf[g][ni].w : bf[g][ni].y);
                    mma_tf32(acc[g][0][ni], a0, b0, b1);
                    mma_tf32(acc[g][1][ni], a1, b0, b1);
                }
        }
    }
}

// ---------------- kernel 0: edge_index dtype detection ----------------------
__global__ void detect_kernel(const int* __restrict__ idx) {
    if (threadIdx.x == 0) {
        int nz = 0;
        #pragma unroll 1
        for (int i = 0; i < 64; ++i) nz |= idx[2 * i + 1];
        g_is64 = (nz == 0) ? 1 : 0;
    }
}

// ---------------- kernel 1: zero init ----------------------------------------
__global__ void init_kernel() {
    size_t i = (size_t)blockIdx.x * blockDim.x + threadIdx.x;
    if (i < (size_t)NNODES * DMODEL / 4)
        ((float4*)g_S)[i] = make_float4(0.f, 0.f, 0.f, 0.f);
    if (i < (size_t)NNODES)
        ((float4*)g_den)[i] = make_float4(0.f, 0.f, 0.f, 0.f);
}

// ---------------- kernel 2: weight prep --------------------------------------
// transpose + tf32 + paired-k permutation + bank swizzle (all 4 matrices)
__global__ void prep_kernel(const float* __restrict__ Wq, const float* __restrict__ Wk,
                            const float* __restrict__ Wv, const float* __restrict__ Wo) {
    __shared__ float t[32][33];
    const float* W[4] = {Wq, Wk, Wv, Wo};
    int w = blockIdx.z, k0 = blockIdx.x * 32, n0 = blockIdx.y * 32;
    int tx = threadIdx.x, ty = threadIdx.y;      // 32 x 8
    const float* src = W[w];
    #pragma unroll
    for (int j = 0; j < 32; j += 8)
        t[ty + j][tx] = to_tf32(src[(k0 + ty + j) * DMODEL + n0 + tx]);
    __syncthreads();
    #pragma unroll
    for (int j = 0; j < 32; j += 8) {
        int n = n0 + ty + j;
        int k = k0 + tx;
        int kp = (k & ~15) | ((k & 3) << 2) | (((k >> 3) & 1) << 1) | ((k >> 2) & 1);
        g_Wt[w][n][kp ^ ((n & 1) << 4)] = t[tx][ty + j];
    }
}

// ---------------- kernel 3: persistent fused QKV + scores + scatter ----------
__global__ __launch_bounds__(256, 1)
void fusedP_kernel(const float* __restrict__ X, const void* __restrict__ idx,
                   const float* __restrict__ bq, const float* __restrict__ bk,
                   const float* __restrict__ bv) {
    extern __shared__ float sm[];
    float* As = sm;                  // [64][128] swizzled X tile
    float* Wq_ = sm + 64 * 128;      // 3 x [128][128] paired-k weights
    float* Wk_ = Wq_ + 128 * 128;
    float* Wv_ = Wk_ + 128 * 128;

    int tid = threadIdx.x, lane = tid & 31, warp = tid >> 5;
    int wm = warp & 1, wn = warp >> 1, gr = lane >> 2, tg = lane & 3;
    int is64 = g_is64;
    unsigned asB = (unsigned)__cvta_generic_to_shared(As);

    // one-time: weights + first A tile
    for (int i = tid; i < 3 * 4096; i += 256)
        cp_async16(Wq_ + i * 4, ((const float*)g_Wt) + i * 4);
    {
        size_t e0 = (size_t)blockIdx.x * 64;
        for (int i = tid; i < 2048; i += 256) {
            int r = i >> 5, c = (i & 31) << 2;
            cp_async16(As + r * 128 + (c ^ ((r & 7) << 2)),
                       X + (e0 + r) * DMODEL + c);
        }
    }
    cp_commit();
    cp_wait<0>();
    __syncthreads();

    // loop-invariant bias fragments
    float2 bqr[4], bkr[4], bvr[4];
    #pragma unroll
    for (int ni = 0; ni < 4; ++ni) {
        int col = wn * 32 + ni * 8 + tg * 2;
        bqr[ni] = make_float2(__ldg(bq + col), __ldg(bq + col + 1));
        bkr[ni] = make_float2(__ldg(bk + col), __ldg(bk + col + 1));
        bvr[ni] = make_float2(__ldg(bv + col), __ldg(bv + col + 1));
    }

    for (int t = blockIdx.x; t < NTILES; t += PGRID) {
        size_t e0 = (size_t)t * 64;

        // prefetch this tile's edge indices (hidden under the GEMM)
        int srcR[2][2], dstR[2][2];
        #pragma unroll
        for (int mi = 0; mi < 2; ++mi)
            #pragma unroll
            for (int sr = 0; sr < 2; ++sr) {
                int row = wm * 32 + mi * 16 + sr * 8 + gr;
                srcR[mi][sr] = node_of(idx, is64, e0 + row);
                dstR[mi][sr] = node_of(idx, is64, (size_t)E_EDGES + e0 + row);
            }

        // ---- pass 1: Q + K GEMMs (fused, low register pressure) ----
        float accQK[2][2][4][4];
        gemm_core<2>(asB, Wq_, Wk_, accQK, wm, wn, lane);

        // scores for head wn: (Q+bq).(K+bk), quad shuffle, exp
        float ev[4];
        #pragma unroll
        for (int mi = 0; mi < 2; ++mi) {
            float s0 = 0.f, s1 = 0.f;
            #pragma unroll
            for (int ni = 0; ni < 4; ++ni) {
                s0 += (accQK[0][mi][ni][0] + bqr[ni].x) * (accQK[1][mi][ni][0] + bkr[ni].x)
                    + (accQK[0][mi][ni][1] + bqr[ni].y) * (accQK[1][mi][ni][1] + bkr[ni].y);
                s1 += (accQK[0][mi][ni][2] + bqr[ni].x) * (accQK[1][mi][ni][2] + bkr[ni].x)
                    + (accQK[0][mi][ni][3] + bqr[ni].y) * (accQK[1][mi][ni][3] + bkr[ni].y);
            }
            s0 += __shfl_xor_sync(0xffffffffu, s0, 1);
            s0 += __shfl_xor_sync(0xffffffffu, s0, 2);
            s1 += __shfl_xor_sync(0xffffffffu, s1, 1);
            s1 += __shfl_xor_sync(0xffffffffu, s1, 2);
            ev[mi * 2]     = __expf(s0 * SCALEF);
            ev[mi * 2 + 1] = __expf(s1 * SCALEF);
        }

        // ---- pass 2: V GEMM ----
        float accV[1][2][4][4];
        gemm_core<1>(asB, Wv_, Wv_, accV, wm, wn, lane);

        __syncthreads();   // all warps done reading As

        // stream next A tile straight into smem
        int tn = t + PGRID;
        if (tn < NTILES) {
            size_t en = (size_t)tn * 64;
            for (int i = tid; i < 2048; i += 256) {
                int r = i >> 5, c = (i & 31) << 2;
                cp_async16(As + r * 128 + (c ^ ((r & 7) << 2)),
                           X + (en + r) * DMODEL + c);
            }
            cp_commit();
        }

        // scatter: weighted V to src & dst, den per head (fire-and-forget REDG)
        #pragma unroll
        for (int mi = 0; mi < 2; ++mi) {
            #pragma unroll
            for (int sr = 0; sr < 2; ++sr) {
                int src = srcR[mi][sr], dst = dstR[mi][sr];
                float* ps = g_S + (size_t)src * DMODEL;
                float* pd = g_S + (size_t)dst * DMODEL;
                float w = ev[mi * 2 + sr];
                if (tg == 0) {
                    red_add_f(&g_den[(size_t)src * 4 + wn], w);
                    red_add_f(&g_den[(size_t)dst * 4 + wn], w);
                }
                #pragma unroll
                for (int ni = 0; ni < 4; ++ni) {
                    int col = wn * 32 + ni * 8 + tg * 2;
                    float v0 = (accV[0][mi][ni][sr * 2]     + bvr[ni].x) * w;
                    float v1 = (accV[0][mi][ni][sr * 2 + 1] + bvr[ni].y) * w;
                    float p0 = __shfl_xor_sync(0xffffffffu, v0, 1);
                    float p1 = __shfl_xor_sync(0xffffffffu, v1, 1);
                    if (!(tg & 1)) {
                        red_add_v4(ps + col, v0, v1, p0, p1);
                        red_add_v4(pd + col, v0, v1, p0, p1);
                    }
                }
            }
        }

        cp_wait<0>();
        __syncthreads();   // next As ready
    }
}

// ---------------- kernel 4: per-NODE Wo GEMM: T = (0.5*S/den) @ Wo -----------
// 64-row node tiles, 96KB smem -> 2 CTAs/SM.
__global__ __launch_bounds__(256, 2)
void nodeT_kernel() {
    extern __shared__ float sm[];
    float* Ms = sm;                  // [64][128] swizzled node msg tile
    float* Wo_ = sm + 64 * 128;      // [128][128] paired-k Wo

    int tid = threadIdx.x, lane = tid & 31, warp = tid >> 5;
    int wm = warp & 1, wn = warp >> 1, gr = lane >> 2, tg = lane & 3;
    size_t n0 = (size_t)blockIdx.x * 64;
    unsigned msB = (unsigned)__cvta_generic_to_shared(Ms);

    for (int i = tid; i < 4096; i += 256)
        cp_async16(Wo_ + i * 4, ((const float*)g_Wt[3]) + i * 4);
    cp_commit();

    {   // build tile: 4 threads per row, one head (32 cols) each
        int r = tid >> 2, hd = tid & 3;
        size_t node = n0 + r;
        float d = g_den[node * 4 + hd];
        float f = (d > 0.f) ? 0.5f / d : 0.f;
        const float* Sp = g_S + node * DMODEL + hd * 32;
        int s = (r & 7) << 2;
        #pragma unroll
        for (int j = 0; j < 8; ++j) {
            int c = hd * 32 + j * 4;
            float4 a = *(const float4*)(Sp + j * 4);
            *(float4*)(Ms + r * 128 + (c ^ s)) =
                make_float4(a.x * f, a.y * f, a.z * f, a.w * f);
        }
    }
    cp_wait<0>();
    __syncthreads();

    float acc[1][2][4][4];
    gemm_core<1>(msB, Wo_, Wo_, acc, wm, wn, lane);

    #pragma unroll
    for (int mi = 0; mi < 2; ++mi) {
        int r0 = wm * 32 + mi * 16 + gr;
        #pragma unroll
        for (int ni = 0; ni < 4; ++ni) {
            int col = wn * 32 + ni * 8 + tg * 2;
            *(float2*)(g_T + (n0 + r0) * DMODEL + col)     = make_float2(acc[0][mi][ni][0], acc[0][mi][ni][1]);
            *(float2*)(g_T + (n0 + r0 + 8) * DMODEL + col) = make_float2(acc[0][mi][ni][2], acc[0][mi][ni][3]);
        }
    }
}

// ---------------- kernel 5: edge epilogue: LN(T[src]+T[dst]+bo+X) ------------
__global__ __launch_bounds__(256)
void epi_kernel(const void* __restrict__ idx, const float* __restrict__ X,
                const float* __restrict__ bo, const float* __restrict__ gamma,
                const float* __restrict__ beta, float* __restrict__ out) {
    int tid = threadIdx.x, lane = tid & 31;
    size_t e = (size_t)blockIdx.x * 8 + (tid >> 5);
    int is64 = g_is64;

    int src = node_of(idx, is64, e);
    int dst = node_of(idx, is64, (size_t)E_EDGES + e);

    int c = lane * 4;
    float4 ts = *(const float4*)(g_T + (size_t)src * DMODEL + c);
    float4 td = *(const float4*)(g_T + (size_t)dst * DMODEL + c);
    float4 x4 = *(const float4*)(X + e * DMODEL + c);
    float4 b4 = *(const float4*)(bo + c);

    float4 v;
    v.x = ts.x + td.x + b4.x + x4.x;
    v.y = ts.y + td.y + b4.y + x4.y;
    v.z = ts.z + td.z + b4.z + x4.z;
    v.w = ts.w + td.w + b4.w + x4.w;

    float s = v.x + v.y + v.z + v.w;
    float q = v.x * v.x + v.y * v.y + v.z * v.z + v.w * v.w;
    #pragma unroll
    for (int o = 16; o > 0; o >>= 1) {
        s += __shfl_xor_sync(0xffffffffu, s, o);
        q += __shfl_xor_sync(0xffffffffu, q, o);
    }
    float mu = s * (1.0f / 128.0f);
    float var = q * (1.0f / 128.0f) - mu * mu;
    float rstd = rsqrtf(var + LN_EPSF);

    float4 g4 = *(const float4*)(gamma + c);
    float4 be = *(const float4*)(beta + c);
    float4 o4;
    o4.x = (v.x - mu) * rstd * g4.x + be.x;
    o4.y = (v.y - mu) * rstd * g4.y + be.y;
    o4.z = (v.z - mu) * rstd * g4.z + be.z;
    o4.w = (v.w - mu) * rstd * g4.w + be.w;
    *(float4*)(out + e * DMODEL + c) = o4;
}

// ---------------- host -------------------------------------------------------
#define SMEM_P     ((64 * 128 + 3 * 128 * 128) * 4)
#define SMEM_NODE  ((64 * 128 + 128 * 128) * 4)

extern "C" void kernel_launch(void* const* d_in, const int* in_sizes, int n_in,
                              void* d_out, int out_size) {
    const float* X   = (const float*)d_in[0];
    const void*  idx = d_in[1];
    int base = 2;
    if (n_in >= 13 && in_sizes[2] == 1) base = 3;
    const float* Wq    = (const float*)d_in[base + 0];
    const float* bq    = (const float*)d_in[base + 1];
    const float* Wk    = (const float*)d_in[base + 2];
    const float* bk    = (const float*)d_in[base + 3];
    const float* Wv    = (const float*)d_in[base + 4];
    const float* bv    = (const float*)d_in[base + 5];
    const float* Wo    = (const float*)d_in[base + 6];
    const float* bo    = (const float*)d_in[base + 7];
    const float* gamma = (const float*)d_in[base + 8];
    const float* beta  = (const float*)d_in[base + 9];
    float* out = (float*)d_out;

    cudaFuncSetAttribute(fusedP_kernel, cudaFuncAttributeMaxDynamicSharedMemorySize, SMEM_P);
    cudaFuncSetAttribute(nodeT_kernel,  cudaFuncAttributeMaxDynamicSharedMemorySize, SMEM_NODE);

    detect_kernel<<<1, 32>>>((const int*)idx);
    init_kernel<<<8192, 256>>>();
    prep_kernel<<<dim3(4, 4, 4), dim3(32, 8)>>>(Wq, Wk, Wv, Wo);
    fusedP_kernel<<<PGRID, 256, SMEM_P>>>(X, idx, bq, bk, bv);
    nodeT_kernel<<<NNODES / 64, 256, SMEM_NODE>>>();
    epi_kernel<<<E_EDGES / 8, 256>>>(idx, X, bo, gamma, beta, out);
}

// round 11
// speedup vs baseline: 1.1413x; 1.1413x over previous
#include <cuda_runtime.h>
#include <cuda_bf16.h>

#define E_EDGES 262144
#define DMODEL  128
#define NNODES  65536
#define LN_EPSF 1e-5f
#define SCALEF  0.17677669529663687f   // 1/sqrt(32)
#define NTILES  4096                   // 64-edge tiles
#define PGRID   152

// ---------------- scratch (device globals; no allocations allowed) ----------
__device__ float g_S[(size_t)NNODES * DMODEL];       // sum exp(s)*V per node
__device__ float g_den[(size_t)NNODES * 4];          // sum exp(s) per node/head
__device__ float g_T[(size_t)NNODES * DMODEL];       // (0.5*S/den) @ Wo per node
__device__ __nv_bfloat16 g_Wb[4][DMODEL][DMODEL];    // bf16, transposed, paired-k+swz
__device__ int   g_is64;

// ---------------- helpers ----------------------------------------------------
__device__ __forceinline__ void mma_bf16(float c[4], const unsigned a[4],
                                         unsigned b0, unsigned b1) {
    asm volatile(
        "mma.sync.aligned.m16n8k16.row.col.f32.bf16.bf16.f32 "
        "{%0,%1,%2,%3}, {%4,%5,%6,%7}, {%8,%9}, {%0,%1,%2,%3};"
        : "+f"(c[0]), "+f"(c[1]), "+f"(c[2]), "+f"(c[3])
        : "r"(a[0]), "r"(a[1]), "r"(a[2]), "r"(a[3]), "r"(b0), "r"(b1));
}

__device__ __forceinline__ void ldsm4(unsigned r[4], unsigned addr) {
    asm volatile("ldmatrix.sync.aligned.m8n8.x4.shared.b16 {%0,%1,%2,%3}, [%4];"
                 : "=r"(r[0]), "=r"(r[1]), "=r"(r[2]), "=r"(r[3]) : "r"(addr));
}

__device__ __forceinline__ unsigned pack_bf16(float lo, float hi) {
    __nv_bfloat162 h = __floats2bfloat162_rn(lo, hi);   // .x = lo (low 16 bits)
    return *(unsigned*)&h;
}

__device__ __forceinline__ void red_add_v4(float* p, float x, float y, float z, float w) {
    asm volatile("red.global.add.v4.f32 [%0], {%1,%2,%3,%4};"
                 :: "l"(p), "f"(x), "f"(y), "f"(z), "f"(w) : "memory");
}
__device__ __forceinline__ void red_add_f(float* p, float v) {
    asm volatile("red.global.add.f32 [%0], %1;" :: "l"(p), "f"(v) : "memory");
}

__device__ __forceinline__ void cp_async16(void* smem_dst, const void* gsrc) {
    unsigned s = (unsigned)__cvta_generic_to_shared(smem_dst);
    asm volatile("cp.async.cg.shared.global [%0], [%1], 16;" :: "r"(s), "l"(gsrc));
}
__device__ __forceinline__ void cp_commit() {
    asm volatile("cp.async.commit_group;");
}
template <int N>
__device__ __forceinline__ void cp_wait() {
    asm volatile("cp.async.wait_group %0;" :: "n"(N));
}

__device__ __forceinline__ int node_of(const void* idx, int is64, size_t pos) {
    return is64 ? (int)__ldg((const long long*)idx + pos)
                : __ldg((const int*)idx + pos);
}

__device__ __forceinline__ int swzB(int n) {        // B quantum swizzle
    return ((n & 1) << 2) | ((n >> 1) & 3);
}

// bf16 GEMM core over a 64-row A tile (bf16, 256B rows, quantum^(r&7) swizzle)
// and G weight matrices (paired-k layout). Per warp: m = 16*M rows, n32.
// A via ldmatrix.x4; B via one LDS.128 per (g,ni) covering TWO k16 steps.
template <int G, int M>
__device__ __forceinline__ void gemm_bf16(unsigned asB,
                                          const __nv_bfloat16* W0,
                                          const __nv_bfloat16* W1,
                                          float acc[G][M][4][4],
                                          int mbase, int wn, int lane) {
    const __nv_bfloat16* Wg[2] = {W0, W1};
    int tg = lane & 3, gr = lane >> 2;
    int li = lane & 7, lj = (lane >> 3) & 1, qb = lane >> 4;
    int arow = mbase + lj * 8 + li;                 // mbase multiple of 16
    int rsw = arow & 7;
    unsigned aBase = asB + (unsigned)arow * 256u;

    #pragma unroll
    for (int g = 0; g < G; ++g)
        #pragma unroll
        for (int mi = 0; mi < M; ++mi)
            #pragma unroll
            for (int ni = 0; ni < 4; ++ni)
                #pragma unroll
                for (int q = 0; q < 4; ++q) acc[g][mi][ni][q] = 0.f;

    #pragma unroll
    for (int p = 0; p < 4; ++p) {                   // k32 groups
        float4 bf[G][4];
        #pragma unroll
        for (int g = 0; g < G; ++g)
            #pragma unroll
            for (int ni = 0; ni < 4; ++ni) {
                int n = wn * 32 + ni * 8 + gr;
                bf[g][ni] = *(const float4*)((const char*)Wg[g] + n * 256 +
                              (((p * 4 + tg) ^ swzB(n)) << 4));
            }
        #pragma unroll
        for (int sh = 0; sh < 2; ++sh) {            // two k16 steps per group
            int s = p * 2 + sh;
            unsigned koff = (unsigned)(((2 * s + qb) ^ rsw) << 4);
            unsigned a[M][4];
            #pragma unroll
            for (int mi = 0; mi < M; ++mi)
                ldsm4(a[mi], aBase + (unsigned)(mi * 16 * 256) + koff);
            #pragma unroll
            for (int g = 0; g < G; ++g)
                #pragma unroll
                for (int ni = 0; ni < 4; ++ni) {
                    unsigned b0 = __float_as_uint(sh ? bf[g][ni].z : bf[g][ni].x);
                    unsigned b1 = __float_as_uint(sh ? bf[g][ni].w : bf[g][ni].y);
                    #pragma unroll
                    for (int mi = 0; mi < M; ++mi)
                        mma_bf16(acc[g][mi][ni], a[mi], b0, b1);
                }
        }
    }
}

// ---------------- kernel 0: edge_index dtype detection ----------------------
__global__ void detect_kernel(const int* __restrict__ idx) {
    if (threadIdx.x == 0) {
        int nz = 0;
        #pragma unroll 1
        for (int i = 0; i < 64; ++i) nz |= idx[2 * i + 1];
        g_is64 = (nz == 0) ? 1 : 0;
    }
}

// ---------------- kernel 1: zero init ----------------------------------------
__global__ void init_kernel() {
    size_t i = (size_t)blockIdx.x * blockDim.x + threadIdx.x;
    if (i < (size_t)NNODES * DMODEL / 4)
        ((float4*)g_S)[i] = make_float4(0.f, 0.f, 0.f, 0.f);
    if (i < (size_t)NNODES)
        ((float4*)g_den)[i] = make_float4(0.f, 0.f, 0.f, 0.f);
}

// ---------------- kernel 2: weight prep --------------------------------------
// W^T[n][k] in bf16 with paired-k permutation (within each k32 group:
// newr = ((r>>1)&3)*8 + (r>>3)*2 + (r&1)) and quantum swizzle ^swzB(n).
__global__ void prep_kernel(const float* __restrict__ Wq, const float* __restrict__ Wk,
                            const float* __restrict__ Wv, const float* __restrict__ Wo) {
    __shared__ float t[32][33];
    const float* W[4] = {Wq, Wk, Wv, Wo};
    int w = blockIdx.z, k0 = blockIdx.x * 32, n0 = blockIdx.y * 32;
    int tx = threadIdx.x, ty = threadIdx.y;      // 32 x 8
    const float* src = W[w];
    #pragma unroll
    for (int j = 0; j < 32; j += 8)
        t[ty + j][tx] = src[(k0 + ty + j) * DMODEL + n0 + tx];
    __syncthreads();
    #pragma unroll
    for (int j = 0; j < 32; j += 8) {
        int n = n0 + ty + j;
        int k = k0 + tx;
        int r = k & 31;
        int newr = ((r >> 1) & 3) * 8 + ((r >> 3) << 1) + (r & 1);
        int klog = (k & ~31) | newr;
        int kphys = ((klog >> 3) ^ swzB(n)) * 8 + (klog & 7);
        g_Wb[w][n][kphys] = __float2bfloat16(t[tx][ty + j]);
    }
}

// ---------------- kernel 3: persistent fused QKV + scores + scatter ----------
// 152 CTAs x 512 thr (16 warps). Warp grid 4m x 4n, per-warp m16 x n32.
// Weights (96KB bf16) resident; X staged fp32 via cp.async, converted to bf16.
__global__ __launch_bounds__(512, 1)
void fusedP_kernel(const float* __restrict__ X, const void* __restrict__ idx,
                   const float* __restrict__ bq, const float* __restrict__ bk,
                   const float* __restrict__ bv) {
    extern __shared__ char smc[];
    __nv_bfloat16* As  = (__nv_bfloat16*)smc;              // [64][128] bf16
    __nv_bfloat16* Wq_ = As + 64 * 128;                    // 3 x [128][128] bf16
    __nv_bfloat16* Wk_ = Wq_ + 128 * 128;
    __nv_bfloat16* Wv_ = Wk_ + 128 * 128;
    float* Xs = (float*)(Wv_ + 128 * 128);                 // [64][128] fp32 staging

    int tid = threadIdx.x, lane = tid & 31, warp = tid >> 5;
    int wm = warp & 3, wn = warp >> 2, gr = lane >> 2, tg = lane & 3;
    int mbase = wm * 16;
    int is64 = g_is64;
    unsigned asB = (unsigned)__cvta_generic_to_shared(As);

    // one-time: 3 weight matrices (contiguous) + first X tile into staging
    for (int i = tid; i < 6144; i += 512)
        cp_async16((float*)Wq_ + i * 4, (const float*)g_Wb + i * 4);
    {
        size_t e0 = (size_t)blockIdx.x * 64;
        for (int i = tid; i < 2048; i += 512) {
            int r = i >> 5, c = (i & 31) << 2;
            cp_async16(Xs + r * 128 + c, X + (e0 + r) * DMODEL + c);
        }
    }
    cp_commit();
    cp_wait<0>();
    __syncthreads();

    // conversion roles: thread -> (row pr, 2 quanta starting at qs)
    int pr = tid >> 3, qs = (tid & 7) * 2;
    {   // build first As from staging
        #pragma unroll
        for (int j = 0; j < 2; ++j) {
            int q = qs + j;
            float4 x0 = *(const float4*)(Xs + pr * 128 + q * 8);
            float4 x1 = *(const float4*)(Xs + pr * 128 + q * 8 + 4);
            uint4 u;
            u.x = pack_bf16(x0.x, x0.y); u.y = pack_bf16(x0.z, x0.w);
            u.z = pack_bf16(x1.x, x1.y); u.w = pack_bf16(x1.z, x1.w);
            *(uint4*)((char*)As + pr * 256 + ((q ^ (pr & 7)) << 4)) = u;
        }
    }
    __syncthreads();

    // loop-invariant bias fragments (fp32, added post-GEMM)
    float2 bqr[4], bkr[4], bvr[4];
    #pragma unroll
    for (int ni = 0; ni < 4; ++ni) {
        int col = wn * 32 + ni * 8 + tg * 2;
        bqr[ni] = make_float2(__ldg(bq + col), __ldg(bq + col + 1));
        bkr[ni] = make_float2(__ldg(bk + col), __ldg(bk + col + 1));
        bvr[ni] = make_float2(__ldg(bv + col), __ldg(bv + col + 1));
    }

    for (int t = blockIdx.x; t < NTILES; t += PGRID) {
        size_t e0 = (size_t)t * 64;
        int tn = t + PGRID;
        bool hasNext = tn < NTILES;

        // stream next X tile (fp32) into staging while we compute
        if (hasNext) {
            size_t en = (size_t)tn * 64;
            for (int i = tid; i < 2048; i += 512) {
                int r = i >> 5, c = (i & 31) << 2;
                cp_async16(Xs + r * 128 + c, X + (en + r) * DMODEL + c);
            }
            cp_commit();
        }

        // prefetch this tile's edge indices
        int srcR[2], dstR[2];
        #pragma unroll
        for (int sr = 0; sr < 2; ++sr) {
            int row = mbase + sr * 8 + gr;
            srcR[sr] = node_of(idx, is64, e0 + row);
            dstR[sr] = node_of(idx, is64, (size_t)E_EDGES + e0 + row);
        }

        // pass 1: Q + K
        float accQK[2][1][4][4];
        gemm_bf16<2, 1>(asB, Wq_, Wk_, accQK, mbase, wn, lane);

        // scores for head wn, exp
        float ev[2];
        {
            float s0 = 0.f, s1 = 0.f;
            #pragma unroll
            for (int ni = 0; ni < 4; ++ni) {
                s0 += (accQK[0][0][ni][0] + bqr[ni].x) * (accQK[1][0][ni][0] + bkr[ni].x)
                    + (accQK[0][0][ni][1] + bqr[ni].y) * (accQK[1][0][ni][1] + bkr[ni].y);
                s1 += (accQK[0][0][ni][2] + bqr[ni].x) * (accQK[1][0][ni][2] + bkr[ni].x)
                    + (accQK[0][0][ni][3] + bqr[ni].y) * (accQK[1][0][ni][3] + bkr[ni].y);
            }
            s0 += __shfl_xor_sync(0xffffffffu, s0, 1);
            s0 += __shfl_xor_sync(0xffffffffu, s0, 2);
            s1 += __shfl_xor_sync(0xffffffffu, s1, 1);
            s1 += __shfl_xor_sync(0xffffffffu, s1, 2);
            ev[0] = __expf(s0 * SCALEF);
            ev[1] = __expf(s1 * SCALEF);
        }

        // pass 2: V
        float accV[1][1][4][4];
        gemm_bf16<1, 1>(asB, Wv_, Wv_, accV, mbase, wn, lane);

        __syncthreads();          // all warps done reading As

        // convert staged X -> As (bf16, swizzled)
        if (hasNext) {
            cp_wait<0>();
            #pragma unroll
            for (int j = 0; j < 2; ++j) {
                int q = qs + j;
                float4 x0 = *(const float4*)(Xs + pr * 128 + q * 8);
                float4 x1 = *(const float4*)(Xs + pr * 128 + q * 8 + 4);
                uint4 u;
                u.x = pack_bf16(x0.x, x0.y); u.y = pack_bf16(x0.z, x0.w);
                u.z = pack_bf16(x1.x, x1.y); u.w = pack_bf16(x1.z, x1.w);
                *(uint4*)((char*)As + pr * 256 + ((q ^ (pr & 7)) << 4)) = u;
            }
        }

        // scatter: weighted V to src & dst, den per head (fire-and-forget)
        #pragma unroll
        for (int sr = 0; sr < 2; ++sr) {
            int src = srcR[sr], dst = dstR[sr];
            float* ps = g_S + (size_t)src * DMODEL;
            float* pd = g_S + (size_t)dst * DMODEL;
            float w = ev[sr];
            if (tg == 0) {
                red_add_f(&g_den[(size_t)src * 4 + wn], w);
                red_add_f(&g_den[(size_t)dst * 4 + wn], w);
            }
            #pragma unroll
            for (int ni = 0; ni < 4; ++ni) {
                int col = wn * 32 + ni * 8 + tg * 2;
                float v0 = (accV[0][0][ni][sr * 2]     + bvr[ni].x) * w;
                float v1 = (accV[0][0][ni][sr * 2 + 1] + bvr[ni].y) * w;
                float p0 = __shfl_xor_sync(0xffffffffu, v0, 1);
                float p1 = __shfl_xor_sync(0xffffffffu, v1, 1);
                if (!(tg & 1)) {
                    red_add_v4(ps + col, v0, v1, p0, p1);
                    red_add_v4(pd + col, v0, v1, p0, p1);
                }
            }
        }

        __syncthreads();          // As refilled
    }
}

// ---------------- kernel 4: per-NODE Wo GEMM: T = (0.5*S/den) @ Wo -----------
// 64-row node tiles, bf16 core, 48KB smem -> 2 CTAs/SM, 256 thr (2m x 4n, M=2).
__global__ __launch_bounds__(256, 2)
void nodeT_kernel() {
    extern __shared__ char smc[];
    __nv_bfloat16* Ms  = (__nv_bfloat16*)smc;      // [64][128] bf16 msg tile
    __nv_bfloat16* Wo_ = Ms + 64 * 128;            // [128][128] bf16 Wo

    int tid = threadIdx.x, lane = tid & 31, warp = tid >> 5;
    int wm = warp & 1, wn = warp >> 1, gr = lane >> 2, tg = lane & 3;
    size_t n0 = (size_t)blockIdx.x * 64;
    unsigned msB = (unsigned)__cvta_generic_to_shared(Ms);

    for (int i = tid; i < 2048; i += 256)
        cp_async16((float*)Wo_ + i * 4, (const float*)g_Wb[3] + i * 4);
    cp_commit();

    {   // build tile: 4 threads per row, one head (32 cols = 4 quanta) each
        int r = tid >> 2, hd = tid & 3;
        size_t node = n0 + r;
        float d = g_den[node * 4 + hd];
        float f = (d > 0.f) ? 0.5f / d : 0.f;
        const float* Sp = g_S + node * DMODEL + hd * 32;
        #pragma unroll
        for (int j = 0; j < 4; ++j) {
            int q = hd * 4 + j;
            float4 a = *(const float4*)(Sp + j * 8);
            float4 b = *(const float4*)(Sp + j * 8 + 4);
            uint4 u;
            u.x = pack_bf16(a.x * f, a.y * f); u.y = pack_bf16(a.z * f, a.w * f);
            u.z = pack_bf16(b.x * f, b.y * f); u.w = pack_bf16(b.z * f, b.w * f);
            *(uint4*)((char*)Ms + r * 256 + ((q ^ (r & 7)) << 4)) = u;
        }
    }
    cp_wait<0>();
    __syncthreads();

    float acc[1][2][4][4];
    gemm_bf16<1, 2>(msB, Wo_, Wo_, acc, wm * 32, wn, lane);

    #pragma unroll
    for (int mi = 0; mi < 2; ++mi) {
        int r0 = wm * 32 + mi * 16 + gr;
        #pragma unroll
        for (int ni = 0; ni < 4; ++ni) {
            int col = wn * 32 + ni * 8 + tg * 2;
            *(float2*)(g_T + (n0 + r0) * DMODEL + col)     = make_float2(acc[0][mi][ni][0], acc[0][mi][ni][1]);
            *(float2*)(g_T + (n0 + r0 + 8) * DMODEL + col) = make_float2(acc[0][mi][ni][2], acc[0][mi][ni][3]);
        }
    }
}

// ---------------- kernel 5: edge epilogue: LN(T[src]+T[dst]+bo+X) ------------
__global__ __launch_bounds__(256)
void epi_kernel(const void* __restrict__ idx, const float* __restrict__ X,
                const float* __restrict__ bo, const float* __restrict__ gamma,
                const float* __restrict__ beta, float* __restrict__ out) {
    int tid = threadIdx.x, lane = tid & 31;
    size_t e = (size_t)blockIdx.x * 8 + (tid >> 5);
    int is64 = g_is64;

    int src = node_of(idx, is64, e);
    int dst = node_of(idx, is64, (size_t)E_EDGES + e);

    int c = lane * 4;
    float4 ts = *(const float4*)(g_T + (size_t)src * DMODEL + c);
    float4 td = *(const float4*)(g_T + (size_t)dst * DMODEL + c);
    float4 x4 = *(const float4*)(X + e * DMODEL + c);
    float4 b4 = *(const float4*)(bo + c);

    float4 v;
    v.x = ts.x + td.x + b4.x + x4.x;
    v.y = ts.y + td.y + b4.y + x4.y;
    v.z = ts.z + td.z + b4.z + x4.z;
    v.w = ts.w + td.w + b4.w + x4.w;

    float s = v.x + v.y + v.z + v.w;
    float q = v.x * v.x + v.y * v.y + v.z * v.z + v.w * v.w;
    #pragma unroll
    for (int o = 16; o > 0; o >>= 1) {
        s += __shfl_xor_sync(0xffffffffu, s, o);
        q += __shfl_xor_sync(0xffffffffu, q, o);
    }
    float mu = s * (1.0f / 128.0f);
    float var = q * (1.0f / 128.0f) - mu * mu;
    float rstd = rsqrtf(var + LN_EPSF);

    float4 g4 = *(const float4*)(gamma + c);
    float4 be = *(const float4*)(beta + c);
    float4 o4;
    o4.x = (v.x - mu) * rstd * g4.x + be.x;
    o4.y = (v.y - mu) * rstd * g4.y + be.y;
    o4.z = (v.z - mu) * rstd * g4.z + be.z;
    o4.w = (v.w - mu) * rstd * g4.w + be.w;
    *(float4*)(out + e * DMODEL + c) = o4;
}

// ---------------- host -------------------------------------------------------
#define SMEM_P     ((64 * 128 + 3 * 128 * 128) * 2 + 64 * 128 * 4)   // 112KB + 32KB
#define SMEM_NODE  ((64 * 128 + 128 * 128) * 2)                       // 48KB

extern "C" void kernel_launch(void* const* d_in, const int* in_sizes, int n_in,
                              void* d_out, int out_size) {
    const float* X   = (const float*)d_in[0];
    const void*  idx = d_in[1];
    int base = 2;
    if (n_in >= 13 && in_sizes[2] == 1) base = 3;
    const float* Wq    = (const float*)d_in[base + 0];
    const float* bq    = (const float*)d_in[base + 1];
    const float* Wk    = (const float*)d_in[base + 2];
    const float* bk    = (const float*)d_in[base + 3];
    const float* Wv    = (const float*)d_in[base + 4];
    const float* bv    = (const float*)d_in[base + 5];
    const float* Wo    = (const float*)d_in[base + 6];
    const float* bo    = (const float*)d_in[base + 7];
    const float* gamma = (const float*)d_in[base + 8];
    const float* beta  = (const float*)d_in[base + 9];
    float* out = (float*)d_out;

    cudaFuncSetAttribute(fusedP_kernel, cudaFuncAttributeMaxDynamicSharedMemorySize, SMEM_P);
    cudaFuncSetAttribute(nodeT_kernel,  cudaFuncAttributeMaxDynamicSharedMemorySize, SMEM_NODE);

    detect_kernel<<<1, 32>>>((const int*)idx);
    init_kernel<<<8192, 256>>>();
    prep_kernel<<<dim3(4, 4, 4), dim3(32, 8)>>>(Wq, Wk, Wv, Wo);
    fusedP_kernel<<<PGRID, 512, SMEM_P>>>(X, idx, bq, bk, bv);
    nodeT_kernel<<<NNODES / 64, 256, SMEM_NODE>>>();
    epi_kernel<<<E_EDGES / 8, 256>>>(idx, X, bo, gamma, beta, out);
}